// round 13
// baseline (speedup 1.0000x reference)
#include <cuda_runtime.h>
#include <cuda_fp16.h>
#include <cstdint>

#define D_FEAT   64
#define CHUNKS   16
#define NP       128          // nodes per partition
#define CAP      128          // per-node id-list capacity (Poisson(64): P(>=128) ~ 2e-11)
#define PCAP     9216         // per-partition pair capacity (Poisson(8192) + ~11 sigma)
#define RING     8            // smem staging ring slots per partition
#define MAXP     1024         // max partitions (MAX_NODES / NP)
#define OVF_CAP  4096
#define MAX_NODES 131072
#define P3_BLOCKS 592

// ---------------- scratch (static device globals; no allocation) ------------
__device__ int    g_up_is_i32;
__device__ int    g_down_is_i32;
__device__ int    g_part_cursor[MAXP];
__device__ int2   g_pairs[(long long)MAXP * PCAP];            // (dst, src)
__device__ __half g_xh[(long long)MAX_NODES * D_FEAT];        // fp16 copy of x
__device__ int    g_ovf_cnt;
__device__ int2   g_ovf[OVF_CAP];                             // (dst, src)

__device__ __forceinline__ void push_ovf(int dst, int src) {
    int o = atomicAdd(&g_ovf_cnt, 1);
    if (o < OVF_CAP) g_ovf[o] = make_int2(dst, src);
}

// ---------------- setup: dtype probe + fp16 convert + zero cursors ----------
// Block 0/1: probe up/down (int64 values < 2^31 -> all high words zero;
// int32 random data -> "high words" are random in [0,1e5), ~surely nonzero).
// Blocks >= 2: convert x->fp16 (8 floats/thread) + zero part_cursor/ovf_cnt.
__global__ __launch_bounds__(256) void setup_kernel(
    const float* __restrict__ x, long long n_elems,
    const unsigned long long* __restrict__ up,   long long nw_up,
    const unsigned long long* __restrict__ down, long long nw_down,
    int do_convert)
{
    if (blockIdx.x < 2) {
        const unsigned long long* idx = blockIdx.x ? down : up;
        long long nw = blockIdx.x ? nw_down : nw_up;
        __shared__ unsigned int s_acc;
        if (threadIdx.x == 0) s_acc = 0u;
        __syncthreads();
        unsigned int local = 0;
        long long n = nw < 2048 ? nw : 2048;
        for (long long i = threadIdx.x; i < n; i += blockDim.x)
            local |= (unsigned int)(idx[i] >> 32);
        #pragma unroll
        for (int o = 16; o > 0; o >>= 1) local |= __shfl_down_sync(~0u, local, o);
        if ((threadIdx.x & 31) == 0 && local) atomicOr(&s_acc, local);
        __syncthreads();
        if (threadIdx.x == 0) {
            int f = (s_acc != 0u) ? 1 : 0;
            if (blockIdx.x) g_down_is_i32 = f; else g_up_is_i32 = f;
        }
        return;
    }
    long long u = (long long)(blockIdx.x - 2) * 256 + threadIdx.x;
    if (u < MAXP) g_part_cursor[u] = 0;
    else if (u == MAXP) g_ovf_cnt = 0;
    if (do_convert) {
        long long i = u * 8;
        if (i + 8 <= n_elems) {
            float4 a = *reinterpret_cast<const float4*>(x + i);
            float4 b = *reinterpret_cast<const float4*>(x + i + 4);
            __half2 h0 = __float22half2_rn(make_float2(a.x, a.y));
            __half2 h1 = __float22half2_rn(make_float2(a.z, a.w));
            __half2 h2 = __float22half2_rn(make_float2(b.x, b.y));
            __half2 h3 = __float22half2_rn(make_float2(b.z, b.w));
            uint4 packed;
            packed.x = *reinterpret_cast<unsigned int*>(&h0);
            packed.y = *reinterpret_cast<unsigned int*>(&h1);
            packed.z = *reinterpret_cast<unsigned int*>(&h2);
            packed.w = *reinterpret_cast<unsigned int*>(&h3);
            *reinterpret_cast<uint4*>(g_xh + i) = packed;
        }
    }
}

// ---------------- pass 3: partition-staged edge scatter ----------------------
// Batch-synchronous: each batch, 256 threads append (dst,src) into per-partition
// smem rings (smem atomics); after __syncthreads, per-partition owner threads
// flush full groups of 4 pairs (32B) with ONE global cursor atomic per group.
// Phases are separated by barriers -> no spinning, no data races.
__global__ __launch_bounds__(256) void partition_kernel(
    const void* __restrict__ up,   long long E_up,
    const void* __restrict__ down, long long E_down,
    int n_nodes, int P)
{
    extern __shared__ int dsm[];
    int*  scnt  = dsm;                     // [MAXP] unflushed count
    int*  sbase = dsm + MAXP;              // [MAXP] ring base
    int2* sbuf  = (int2*)(dsm + 2 * MAXP); // [MAXP * RING]

    int tid = threadIdx.x;
    for (int i = tid; i < P; i += 256) { scnt[i] = 0; sbase[i] = 0; }
    __syncthreads();

    const int is32u = g_up_is_i32;
    const int is32d = g_down_is_i32;
    long long total = E_up + E_down;
    long long chunk = (total + gridDim.x - 1) / gridDim.x;
    long long start = (long long)blockIdx.x * chunk;
    long long endi  = start + chunk; if (endi > total) endi = total;
    int nb = (int)((chunk + 255) >> 8);

    for (int bi = 0; bi < nb; bi++) {
        long long e = start + (long long)bi * 256 + tid;
        int src = 0, dst = -1;
        if (e < endi) {
            if (e < E_up) {
                if (is32u) { src = ((const int*)up)[e];       dst = ((const int*)up)[E_up + e]; }
                else { src = (int)((const long long*)up)[e];  dst = (int)((const long long*)up)[E_up + e]; }
            } else {
                long long e2 = e - E_up;
                if (is32d) { src = ((const int*)down)[e2];      dst = ((const int*)down)[E_down + e2]; }
                else { src = (int)((const long long*)down)[e2]; dst = (int)((const long long*)down)[E_down + e2]; }
            }
        }
        if ((unsigned)dst < (unsigned)n_nodes) {
            if ((unsigned)src >= (unsigned)n_nodes) src = 0;   // defensive
            int p = dst >> 7;
            int l = atomicAdd(&scnt[p], 1);
            if (l < RING) {
                sbuf[p * RING + ((sbase[p] + l) & (RING - 1))] = make_int2(dst, src);
            } else {
                atomicSub(&scnt[p], 1);
                int pos = atomicAdd(&g_part_cursor[p], 1);      // rare direct path
                if (pos < PCAP) g_pairs[(long long)p * PCAP + pos] = make_int2(dst, src);
                else push_ovf(dst, src);
            }
        }
        __syncthreads();
        // flush phase: owner thread per partition (phase-separated, plain ops OK)
        for (int p = tid; p < P; p += 256) {
            while (scnt[p] >= 4) {
                int pos = atomicAdd(&g_part_cursor[p], 4);
                int b0 = sbase[p];
                #pragma unroll
                for (int i = 0; i < 4; i++) {
                    int2 pr = sbuf[p * RING + ((b0 + i) & (RING - 1))];
                    if (pos + i < PCAP) g_pairs[(long long)p * PCAP + pos + i] = pr;
                    else push_ovf(pr.x, pr.y);
                }
                sbase[p] = b0 + 4;
                scnt[p] -= 4;
            }
        }
        __syncthreads();
    }
    // drain remainders (<4 per partition)
    for (int p = tid; p < P; p += 256) {
        int c = scnt[p];
        if (c > 0) {
            int pos = atomicAdd(&g_part_cursor[p], c);
            int b0 = sbase[p];
            for (int i = 0; i < c; i++) {
                int2 pr = sbuf[p * RING + ((b0 + i) & (RING - 1))];
                if (pos + i < PCAP) g_pairs[(long long)p * PCAP + pos + i] = pr;
                else push_ovf(pr.x, pr.y);
            }
        }
    }
}

// ---------------- pass 4: per-partition build (smem) + fused gather ----------
// One block per partition: read pairs coalesced, build per-node id lists in
// smem (ATOMS), then gather fp16 rows and WRITE out directly (no pre-zeroing).
__global__ __launch_bounds__(512) void build_gather_kernel(
    float* __restrict__ out, int n_nodes)
{
    extern __shared__ int dsm[];
    int* lcnt = dsm;          // [NP]
    int* lids = dsm + NP;     // [NP * CAP]

    int tid = threadIdx.x;
    int p = blockIdx.x;
    int n0 = p << 7;

    for (int i = tid; i < NP; i += 512) lcnt[i] = 0;
    __syncthreads();

    int cnt = g_part_cursor[p]; if (cnt > PCAP) cnt = PCAP;
    const int2* pp = g_pairs + (long long)p * PCAP;
    for (int i = tid; i < cnt; i += 512) {
        int2 pr = pp[i];
        int ln = pr.x - n0;                  // guaranteed [0, NP)
        int lp = atomicAdd(&lcnt[ln], 1);
        if (lp < CAP) lids[ln * CAP + lp] = pr.y;
        else push_ovf(pr.x, pr.y);
    }
    __syncthreads();

    int g = tid >> 3, c = tid & 7;           // 64 groups of 8 threads
    const long long coff = c * 8;            // half offset within row
    for (int ln = g; ln < NP; ln += 64) {
        int node = n0 + ln;
        if (node >= n_nodes) break;
        int n = lcnt[ln]; if (n > CAP) n = CAP;
        const int* ids = lids + ln * CAP;

        float2 a0 = make_float2(0.f, 0.f), a1 = a0, a2 = a0, a3 = a0;
        int j = 0;
        for (; j + 4 <= n; j += 4) {
            int s0 = ids[j], s1 = ids[j + 1], s2 = ids[j + 2], s3 = ids[j + 3];
            uint4 v0 = *reinterpret_cast<const uint4*>(g_xh + (long long)s0 * D_FEAT + coff);
            uint4 v1 = *reinterpret_cast<const uint4*>(g_xh + (long long)s1 * D_FEAT + coff);
            uint4 v2 = *reinterpret_cast<const uint4*>(g_xh + (long long)s2 * D_FEAT + coff);
            uint4 v3 = *reinterpret_cast<const uint4*>(g_xh + (long long)s3 * D_FEAT + coff);
            #pragma unroll
            for (int k = 0; k < 4; k++) {
                uint4 v = (k == 0) ? v0 : (k == 1) ? v1 : (k == 2) ? v2 : v3;
                float2 f0 = __half22float2(*reinterpret_cast<__half2*>(&v.x));
                float2 f1 = __half22float2(*reinterpret_cast<__half2*>(&v.y));
                float2 f2 = __half22float2(*reinterpret_cast<__half2*>(&v.z));
                float2 f3 = __half22float2(*reinterpret_cast<__half2*>(&v.w));
                a0.x += f0.x; a0.y += f0.y;
                a1.x += f1.x; a1.y += f1.y;
                a2.x += f2.x; a2.y += f2.y;
                a3.x += f3.x; a3.y += f3.y;
            }
        }
        for (; j < n; j++) {
            int s0 = ids[j];
            uint4 v = *reinterpret_cast<const uint4*>(g_xh + (long long)s0 * D_FEAT + coff);
            float2 f0 = __half22float2(*reinterpret_cast<__half2*>(&v.x));
            float2 f1 = __half22float2(*reinterpret_cast<__half2*>(&v.y));
            float2 f2 = __half22float2(*reinterpret_cast<__half2*>(&v.z));
            float2 f3 = __half22float2(*reinterpret_cast<__half2*>(&v.w));
            a0.x += f0.x; a0.y += f0.y;
            a1.x += f1.x; a1.y += f1.y;
            a2.x += f2.x; a2.y += f2.y;
            a3.x += f3.x; a3.y += f3.y;
        }
        float4* op = reinterpret_cast<float4*>(out + (long long)node * D_FEAT + coff);
        op[0] = make_float4(a0.x, a0.y, a1.x, a1.y);
        op[1] = make_float4(a2.x, a2.y, a3.x, a3.y);
    }
}

// ---------------- overflow fixup (no-op when counter == 0) -------------------
__global__ __launch_bounds__(256) void ovf_fixup_kernel(
    const float* __restrict__ x, float* __restrict__ out)
{
    int n = g_ovf_cnt;
    if (n > OVF_CAP) n = OVF_CAP;
    for (int w = blockIdx.x * blockDim.x + threadIdx.x; w < n * CHUNKS;
         w += gridDim.x * blockDim.x) {
        int ent = w >> 4, q = w & 15;
        int2 e = g_ovf[ent];
        float4 v = *reinterpret_cast<const float4*>(x + (long long)e.y * D_FEAT + q * 4);
        float* pdst = out + (long long)e.x * D_FEAT + q * 4;
        asm volatile("red.global.add.v4.f32 [%0], {%1, %2, %3, %4};"
                     :: "l"(pdst), "f"(v.x), "f"(v.y), "f"(v.z), "f"(v.w) : "memory");
    }
}

// ---------------- fallback path (proven R3 atomic scatter) -------------------
__global__ void zero_out_kernel(float4* __restrict__ out, int n4) {
    int i = blockIdx.x * blockDim.x + threadIdx.x;
    if (i < n4) out[i] = make_float4(0.f, 0.f, 0.f, 0.f);
}

__global__ __launch_bounds__(256) void scatter_add_kernel(
    const float* __restrict__ x, const void* __restrict__ idx_raw,
    long long E, int n_nodes, int use_up_flag,
    float* __restrict__ out)
{
    long long tid = (long long)blockIdx.x * blockDim.x + threadIdx.x;
    long long e = tid >> 4;
    int c = (int)(tid & 15);
    if (e >= E) return;
    int is32 = use_up_flag ? g_up_is_i32 : g_down_is_i32;
    int src, dst;
    if (is32) { src = ((const int*)idx_raw)[e];       dst = ((const int*)idx_raw)[E + e]; }
    else { src = (int)((const long long*)idx_raw)[e]; dst = (int)((const long long*)idx_raw)[E + e]; }
    if ((unsigned)src >= (unsigned)n_nodes || (unsigned)dst >= (unsigned)n_nodes) return;
    const float4 v = *reinterpret_cast<const float4*>(x + (long long)src * D_FEAT + c * 4);
    float* pdst = out + (long long)dst * D_FEAT + c * 4;
    asm volatile("red.global.add.v4.f32 [%0], {%1, %2, %3, %4};"
                 :: "l"(pdst), "f"(v.x), "f"(v.y), "f"(v.z), "f"(v.w) : "memory");
}

// ---------------- launch -----------------------------------------------------
extern "C" void kernel_launch(void* const* d_in, const int* in_sizes, int n_in,
                              void* d_out, int out_size)
{
    const float* x    = (const float*)d_in[0];
    const void*  up   = d_in[1];
    const void*  down = d_in[2];
    float* out = (float*)d_out;

    const long long E_up   = (long long)in_sizes[1] / 2;
    const long long E_down = (long long)in_sizes[2] / 2;
    const int n_nodes = out_size / D_FEAT;
    const int n4 = out_size / 4;

    static const int P3_SMEM = 2 * MAXP * 4 + MAXP * RING * 8;     // 73728
    static const int P4_SMEM = (NP + NP * CAP) * 4;                // 66048

    if (n_nodes <= MAX_NODES) {
        cudaFuncSetAttribute(partition_kernel,
                             cudaFuncAttributeMaxDynamicSharedMemorySize, P3_SMEM);
        cudaFuncSetAttribute(build_gather_kernel,
                             cudaFuncAttributeMaxDynamicSharedMemorySize, P4_SMEM);

        int P = (n_nodes + NP - 1) >> 7;
        long long n_elems = (long long)n_nodes * D_FEAT;
        int cvt_blocks = (int)((n_elems / 8 + 255) / 256);
        int zb = (MAXP + 1 + 255) / 256;
        int aux_blocks = cvt_blocks > zb ? cvt_blocks : zb;

        setup_kernel<<<2 + aux_blocks, 256>>>(x, n_elems,
            (const unsigned long long*)up, E_up,
            (const unsigned long long*)down, E_down, 1);

        partition_kernel<<<P3_BLOCKS, 256, P3_SMEM>>>(up, E_up, down, E_down, n_nodes, P);

        build_gather_kernel<<<P, 512, P4_SMEM>>>(out, n_nodes);

        ovf_fixup_kernel<<<16, 256>>>(x, out);
    } else {
        int zb = (MAXP + 1 + 255) / 256;
        setup_kernel<<<2 + zb, 256>>>(x, 0,
            (const unsigned long long*)up, E_up,
            (const unsigned long long*)down, E_down, 0);
        zero_out_kernel<<<(n4 + 255) / 256, 256>>>((float4*)out, n4);
        long long w1 = E_up * CHUNKS, w2 = E_down * CHUNKS;
        scatter_add_kernel<<<(int)((w1 + 255) / 256), 256>>>(x, up,   E_up,   n_nodes, 1, out);
        scatter_add_kernel<<<(int)((w2 + 255) / 256), 256>>>(x, down, E_down, n_nodes, 0, out);
    }
}

// round 14
// speedup vs baseline: 1.8906x; 1.8906x over previous
#include <cuda_runtime.h>
#include <cuda_fp16.h>
#include <cstdint>

#define D_FEAT 64
#define CHUNKS 16
#define CAP    128           // bucket capacity per node (Poisson(64): P(>=128) ~ 2e-11)
#define OVF_CAP 4096

#define MAX_NODES 131072

// ---------------- scratch (static device globals; no allocation) ------------
__device__ int    g_up_is_i32;
__device__ int    g_down_is_i32;
__device__ int    g_cursor [MAX_NODES];
__device__ int    g_srcids [(long long)MAX_NODES * CAP];
__device__ __half g_xh     [(long long)MAX_NODES * D_FEAT];   // fp16 copy of x
__device__ int    g_ovf_cnt;
__device__ int2   g_ovf    [OVF_CAP];                          // (dst, src)

// ---------------- fused setup: probe + zero cursors + fp16 convert ----------
// Blocks 0,1: dtype probe of up/down. int64 indices (< 2^31) -> all high
// words zero; int32 random data -> "high words" random in [0,1e5), ~surely
// nonzero within 2048 samples. Blocks >= 2: zero cursor/ovf_cnt + convert.
__global__ __launch_bounds__(256) void setup_kernel(
    const float* __restrict__ x, long long n_elems,
    const unsigned long long* __restrict__ up,   long long nw_up,
    const unsigned long long* __restrict__ down, long long nw_down,
    int n_nodes, int do_convert)
{
    if (blockIdx.x < 2) {
        const unsigned long long* idx = blockIdx.x ? down : up;
        long long nw = blockIdx.x ? nw_down : nw_up;
        __shared__ unsigned int s_acc;
        if (threadIdx.x == 0) s_acc = 0u;
        __syncthreads();
        unsigned int local = 0;
        long long n = nw < 2048 ? nw : 2048;
        for (long long i = threadIdx.x; i < n; i += blockDim.x)
            local |= (unsigned int)(idx[i] >> 32);
        #pragma unroll
        for (int o = 16; o > 0; o >>= 1) local |= __shfl_down_sync(~0u, local, o);
        if ((threadIdx.x & 31) == 0 && local) atomicOr(&s_acc, local);
        __syncthreads();
        if (threadIdx.x == 0) {
            int f = (s_acc != 0u) ? 1 : 0;
            if (blockIdx.x) g_down_is_i32 = f; else g_up_is_i32 = f;
        }
        return;
    }
    long long u = (long long)(blockIdx.x - 2) * 256 + threadIdx.x;
    if (u < n_nodes) g_cursor[u] = 0;
    if (u == 0) g_ovf_cnt = 0;
    if (do_convert) {
        long long i = u * 8;
        if (i + 8 <= n_elems) {
            float4 a = *reinterpret_cast<const float4*>(x + i);
            float4 b = *reinterpret_cast<const float4*>(x + i + 4);
            __half2 h0 = __float22half2_rn(make_float2(a.x, a.y));
            __half2 h1 = __float22half2_rn(make_float2(a.z, a.w));
            __half2 h2 = __float22half2_rn(make_float2(b.x, b.y));
            __half2 h3 = __float22half2_rn(make_float2(b.z, b.w));
            uint4 packed;
            packed.x = *reinterpret_cast<unsigned int*>(&h0);
            packed.y = *reinterpret_cast<unsigned int*>(&h1);
            packed.z = *reinterpret_cast<unsigned int*>(&h2);
            packed.w = *reinterpret_cast<unsigned int*>(&h3);
            *reinterpret_cast<uint4*>(g_xh + i) = packed;
        }
    }
}

__device__ __forceinline__ int load_idx(const void* raw, long long i, int is32) {
    return is32 ? ((const int*)raw)[i] : (int)((const long long*)raw)[i];
}

// ---------------- bucket scatter: lean hot path (proven R12) -----------------
// Grain-4, both edge sets in one launch. Overflow goes to a tiny (dst,src)
// list handled by ovf_fixup_kernel after gather.
__global__ __launch_bounds__(256, 6) void bucket2_kernel(
    const void* __restrict__ up,   long long E_up,
    const void* __restrict__ down, long long E_down,
    int n_nodes,
    int* __restrict__ cursor, int* __restrict__ srcids,
    int* __restrict__ ovf_cnt, int2* __restrict__ ovf)
{
    long long t = (long long)blockIdx.x * blockDim.x + threadIdx.x;
    long long units_up = (E_up + 3) >> 2;
    long long units_all = units_up + ((E_down + 3) >> 2);
    if (t >= units_all) return;

    const void* idx_raw;
    long long E, u;
    int is32;
    if (t < units_up) { idx_raw = up;   E = E_up;   is32 = g_up_is_i32;   u = t; }
    else              { idx_raw = down; E = E_down; is32 = g_down_is_i32; u = t - units_up; }

    long long e0 = u * 4;
    int s[4], d[4];
    int cnt;
    if (e0 + 4 <= E) {
        cnt = 4;
        if (is32) {
            int4 vs = *reinterpret_cast<const int4*>((const int*)idx_raw + e0);
            s[0] = vs.x; s[1] = vs.y; s[2] = vs.z; s[3] = vs.w;
            if ((E & 3) == 0) {
                int4 vd = *reinterpret_cast<const int4*>((const int*)idx_raw + E + e0);
                d[0] = vd.x; d[1] = vd.y; d[2] = vd.z; d[3] = vd.w;
            } else {
                #pragma unroll
                for (int k = 0; k < 4; k++) d[k] = ((const int*)idx_raw)[E + e0 + k];
            }
        } else {
            const longlong2* ps = reinterpret_cast<const longlong2*>((const long long*)idx_raw + e0);
            longlong2 a = ps[0], b = ps[1];
            s[0] = (int)a.x; s[1] = (int)a.y; s[2] = (int)b.x; s[3] = (int)b.y;
            const longlong2* pd = reinterpret_cast<const longlong2*>((const long long*)idx_raw + E + e0);
            longlong2 c2 = pd[0], f = pd[1];
            d[0] = (int)c2.x; d[1] = (int)c2.y; d[2] = (int)f.x; d[3] = (int)f.y;
        }
    } else {
        cnt = (int)(E - e0);
        for (int k = 0; k < cnt; k++) {
            s[k] = load_idx(idx_raw, e0 + k, is32);
            d[k] = load_idx(idx_raw, E + e0 + k, is32);
        }
    }

    #pragma unroll
    for (int k = 0; k < 4; k++) {
        if (k >= cnt) break;
        if ((unsigned)d[k] >= (unsigned)n_nodes) continue;
        int src = ((unsigned)s[k] < (unsigned)n_nodes) ? s[k] : 0;
        int pos = atomicAdd(&cursor[d[k]], 1);
        if (pos < CAP) {
            srcids[(long long)d[k] * CAP + pos] = src;
        } else {
            int op = atomicAdd(ovf_cnt, 1);
            if (op < OVF_CAP) ovf[op] = make_int2(d[k], src);
        }
    }
}

// ---------------- gather-accumulate from fp16 x, direct write ----------------
// 8 threads per node; thread c owns 8 halves (16B). fp32 accumulation.
// Writes out rows directly (out NOT pre-zeroed; spills applied after by fixup).
__global__ __launch_bounds__(256) void gather_h_kernel(
    const __half* __restrict__ xh,
    const int* __restrict__ cursor,
    const int* __restrict__ srcids,
    float* __restrict__ out, int n_nodes)
{
    long long tid = (long long)blockIdx.x * blockDim.x + threadIdx.x;
    int node = (int)(tid >> 3);
    int c = (int)(tid & 7);
    if (node >= n_nodes) return;

    int n = cursor[node];
    if (n > CAP) n = CAP;
    const int* ids = srcids + (long long)node * CAP;
    const long long coff = c * 8;   // half offset within row

    float2 a0 = make_float2(0.f, 0.f), a1 = a0, a2 = a0, a3 = a0;

    int j = 0;
    for (; j + 4 <= n; j += 4) {
        int s0 = ids[j], s1 = ids[j + 1], s2 = ids[j + 2], s3 = ids[j + 3];
        uint4 v0 = *reinterpret_cast<const uint4*>(xh + (long long)s0 * D_FEAT + coff);
        uint4 v1 = *reinterpret_cast<const uint4*>(xh + (long long)s1 * D_FEAT + coff);
        uint4 v2 = *reinterpret_cast<const uint4*>(xh + (long long)s2 * D_FEAT + coff);
        uint4 v3 = *reinterpret_cast<const uint4*>(xh + (long long)s3 * D_FEAT + coff);
        #pragma unroll
        for (int k = 0; k < 4; k++) {
            uint4 v = (k == 0) ? v0 : (k == 1) ? v1 : (k == 2) ? v2 : v3;
            float2 f0 = __half22float2(*reinterpret_cast<__half2*>(&v.x));
            float2 f1 = __half22float2(*reinterpret_cast<__half2*>(&v.y));
            float2 f2 = __half22float2(*reinterpret_cast<__half2*>(&v.z));
            float2 f3 = __half22float2(*reinterpret_cast<__half2*>(&v.w));
            a0.x += f0.x; a0.y += f0.y;
            a1.x += f1.x; a1.y += f1.y;
            a2.x += f2.x; a2.y += f2.y;
            a3.x += f3.x; a3.y += f3.y;
        }
    }
    for (; j < n; j++) {
        int s0 = ids[j];
        uint4 v = *reinterpret_cast<const uint4*>(xh + (long long)s0 * D_FEAT + coff);
        float2 f0 = __half22float2(*reinterpret_cast<__half2*>(&v.x));
        float2 f1 = __half22float2(*reinterpret_cast<__half2*>(&v.y));
        float2 f2 = __half22float2(*reinterpret_cast<__half2*>(&v.z));
        float2 f3 = __half22float2(*reinterpret_cast<__half2*>(&v.w));
        a0.x += f0.x; a0.y += f0.y;
        a1.x += f1.x; a1.y += f1.y;
        a2.x += f2.x; a2.y += f2.y;
        a3.x += f3.x; a3.y += f3.y;
    }

    float4* op = reinterpret_cast<float4*>(out + (long long)node * D_FEAT + coff);
    op[0] = make_float4(a0.x, a0.y, a1.x, a1.y);
    op[1] = make_float4(a2.x, a2.y, a3.x, a3.y);
}

// ---------------- overflow fixup, AFTER gather (no-op when counter == 0) -----
__global__ __launch_bounds__(256) void ovf_fixup_kernel(
    const float* __restrict__ x, float* __restrict__ out)
{
    int n = g_ovf_cnt;
    if (n > OVF_CAP) n = OVF_CAP;
    for (int w = blockIdx.x * blockDim.x + threadIdx.x; w < n * CHUNKS;
         w += gridDim.x * blockDim.x) {
        int ent = w >> 4, q = w & 15;
        int2 e = g_ovf[ent];
        float4 v = *reinterpret_cast<const float4*>(x + (long long)e.y * D_FEAT + q * 4);
        float* p = out + (long long)e.x * D_FEAT + q * 4;
        asm volatile("red.global.add.v4.f32 [%0], {%1, %2, %3, %4};"
                     :: "l"(p), "f"(v.x), "f"(v.y), "f"(v.z), "f"(v.w) : "memory");
    }
}

// ---------------- fallback path (proven R3 atomic scatter) -------------------
__global__ void zero_out_kernel(float4* __restrict__ out, int n4) {
    int i = blockIdx.x * blockDim.x + threadIdx.x;
    if (i < n4) out[i] = make_float4(0.f, 0.f, 0.f, 0.f);
}

__global__ __launch_bounds__(256) void scatter_add_kernel(
    const float* __restrict__ x, const void* __restrict__ idx_raw,
    long long E, int n_nodes, int use_up_flag,
    float* __restrict__ out)
{
    long long tid = (long long)blockIdx.x * blockDim.x + threadIdx.x;
    long long e = tid >> 4;
    int c = (int)(tid & 15);
    if (e >= E) return;
    int is32 = use_up_flag ? g_up_is_i32 : g_down_is_i32;
    int src, dst;
    if (is32) { src = ((const int*)idx_raw)[e];       dst = ((const int*)idx_raw)[E + e]; }
    else { src = (int)((const long long*)idx_raw)[e]; dst = (int)((const long long*)idx_raw)[E + e]; }
    if ((unsigned)src >= (unsigned)n_nodes || (unsigned)dst >= (unsigned)n_nodes) return;
    const float4 v = *reinterpret_cast<const float4*>(x + (long long)src * D_FEAT + c * 4);
    float* p = out + (long long)dst * D_FEAT + c * 4;
    asm volatile("red.global.add.v4.f32 [%0], {%1, %2, %3, %4};"
                 :: "l"(p), "f"(v.x), "f"(v.y), "f"(v.z), "f"(v.w) : "memory");
}

// ---------------- launch -----------------------------------------------------
extern "C" void kernel_launch(void* const* d_in, const int* in_sizes, int n_in,
                              void* d_out, int out_size)
{
    const float* x    = (const float*)d_in[0];
    const void*  up   = d_in[1];
    const void*  down = d_in[2];
    float* out = (float*)d_out;

    const long long E_up   = (long long)in_sizes[1] / 2;
    const long long E_down = (long long)in_sizes[2] / 2;
    const int n_nodes = out_size / D_FEAT;
    const int n4 = out_size / 4;

    if (n_nodes <= MAX_NODES) {
        long long n_elems = (long long)n_nodes * D_FEAT;
        int cvt_blocks = (int)((n_elems / 8 + 255) / 256);
        int zb = (n_nodes + 255) / 256;
        int aux_blocks = cvt_blocks > zb ? cvt_blocks : zb;

        setup_kernel<<<2 + aux_blocks, 256>>>(x, n_elems,
            (const unsigned long long*)up, E_up,
            (const unsigned long long*)down, E_down, n_nodes, 1);

        int* cursor;  cudaGetSymbolAddress((void**)&cursor,  g_cursor);
        int* srcids;  cudaGetSymbolAddress((void**)&srcids,  g_srcids);
        __half* xh;   cudaGetSymbolAddress((void**)&xh,      g_xh);
        int* ovf_cnt; cudaGetSymbolAddress((void**)&ovf_cnt, g_ovf_cnt);
        int2* ovf;    cudaGetSymbolAddress((void**)&ovf,     g_ovf);

        long long units_all = ((E_up + 3) >> 2) + ((E_down + 3) >> 2);
        bucket2_kernel<<<(int)((units_all + 255) / 256), 256>>>(
            up, E_up, down, E_down, n_nodes, cursor, srcids, ovf_cnt, ovf);

        long long work = (long long)n_nodes * 8;
        gather_h_kernel<<<(int)((work + 255) / 256), 256>>>(xh, cursor, srcids, out, n_nodes);

        ovf_fixup_kernel<<<16, 256>>>(x, out);
    } else {
        setup_kernel<<<2, 256>>>(x, 0,
            (const unsigned long long*)up, E_up,
            (const unsigned long long*)down, E_down, 0, 0);
        zero_out_kernel<<<(n4 + 255) / 256, 256>>>((float4*)out, n4);
        long long w1 = E_up * CHUNKS, w2 = E_down * CHUNKS;
        scatter_add_kernel<<<(int)((w1 + 255) / 256), 256>>>(x, up,   E_up,   n_nodes, 1, out);
        scatter_add_kernel<<<(int)((w2 + 255) / 256), 256>>>(x, down, E_down, n_nodes, 0, out);
    }
}